// round 13
// baseline (speedup 1.0000x reference)
#include <cuda_runtime.h>

#define BB 64
#define SS 512
#define EE 128
#define TT 10

#define NBLK 64   // one block per batch, one per SM

__device__ __forceinline__ float tanh_approx(float x) {
    float y;
    asm("tanh.approx.f32 %0, %1;" : "=f"(y) : "f"(x));
    return y;
}

// ---------------------------------------------------------------------------
// Fully self-contained block: NO global synchronization, NO global scratch.
//   warp 0  : lanes 0-15 = LSTM recurrence (16-lane scheme, shfl mask 0xFFFF)
//             lanes 16-31 = logits + log_softmax consumer (smem sH + sFlag)
//   warps 1-4: pre producer for THIS batch into a 4-chunk smem ring sPre
//             (chunk = 64 steps; fill chunk c once rec finished chunk c-3)
//   warps 5-7: exit after cooperative smem init.
// All handoffs are membar.cta + volatile smem flags — replay-safe trivially.
// ---------------------------------------------------------------------------
__global__ void __launch_bounds__(256, 1) fused_kernel(
    const int* __restrict__ x, const float* __restrict__ emb,
    const float* __restrict__ Wf, const float* __restrict__ bf, const float* __restrict__ thf,
    const float* __restrict__ Wi, const float* __restrict__ bi, const float* __restrict__ thi,
    const float* __restrict__ Wu, const float* __restrict__ bu, const float* __restrict__ thu,
    const float* __restrict__ Wo, const float* __restrict__ bo, const float* __restrict__ tho,
    const float* __restrict__ Wt, const float* __restrict__ bt,
    float* __restrict__ out)
{
    const unsigned HMASK = 0xFFFFu;       // rec half-warp
    const unsigned UMASK = 0xFFFF0000u;   // out half-warp
    int b   = blockIdx.x;
    int tid = threadIdx.x;

    __shared__ float4 sW4[EE * 4];        // packed gate weights [k*4+w] -> (f,i,u,o)
    __shared__ float4 sC4[4];             // bias + theta per wire
    __shared__ float  sPre[4][64 * 16];   // preactivation ring: [chunk&3][so*16 + w*4+g]
    __shared__ float4 sH4[SS];            // rec->out hidden states (8KB)
    __shared__ float  sWt[4 * TT];
    __shared__ float  sbt[TT];
    __shared__ volatile int sFlag;        // # of 64-step chunks rec has completed
    __shared__ volatile int sPreCnt[8];   // producer warps done per chunk (0..4)

    // ---------------- cooperative init (all 8 warps) ----------------
    for (int idx = tid; idx < EE * 4; idx += 256) {
        int k = idx >> 2, w = idx & 3;
        sW4[idx] = make_float4(Wf[k * 4 + w], Wi[k * 4 + w],
                               Wu[k * 4 + w], Wo[k * 4 + w]);
    }
    if (tid < 4) {
        sC4[tid] = make_float4(bf[tid] + thf[tid], bi[tid] + thi[tid],
                               bu[tid] + thu[tid], bo[tid] + tho[tid]);
    }
    if (tid < 4 * TT) sWt[tid] = Wt[tid];
    if (tid < TT) sbt[tid] = bt[tid];
    if (tid == 0) sFlag = 0;
    if (tid < 8) sPreCnt[tid] = 0;
    __syncthreads();

    int wid = tid >> 5;

    if (wid == 0) {
        // ================= REC (lanes 0-15) + OUT (lanes 16-31) =================
        int lane = tid;

        if (lane < 16) {
            // ---- recurrence ----
            int g = lane >> 2;
            int w = lane & 3;

            const float* Wg = (g == 0) ? Wf : (g == 1) ? Wi : (g == 2) ? Wu : Wo;
            float Wh0 = Wg[(128 + 0) * 4 + w];
            float Wh1 = Wg[(128 + 1) * 4 + w];
            float Wh2 = Wg[(128 + 2) * 4 + w];
            float Wh3 = Wg[(128 + 3) * 4 + w];

            const bool m0 = (w != 0);
            const bool m2 = (w == 0) | (w >= 2);
            const bool m3 = (w == 0) | (w == 3);
            const float tsc = (g == 2) ? 1.0f : 0.5f;
            const int gbase = lane & 12;
            const int lo = w * 4 + g;      // lane offset within a step's 16 floats

            float* sH = (float*)sH4;
            float hv = 0.f, cx = 0.f;

            for (int blk = 0; blk < 128; blk++) {
                // entering a new 64-step chunk: wait for all 4 producer warps
                if ((blk & 15) == 0) {
                    int c = blk >> 4;
                    while (sPreCnt[c] < 4) __nanosleep(64);
                    __threadfence_block();
                }

                const float* ps = &sPre[(blk >> 4) & 3][(blk & 15) * 64 + lo];
                float pc0 = ps[0], pc1 = ps[16], pc2 = ps[32], pc3 = ps[48];

                #pragma unroll
                for (int k = 0; k < 4; k++) {
                    float p = (k == 0) ? pc0 : (k == 1) ? pc1 : (k == 2) ? pc2 : pc3;

                    float hx0 = __shfl_sync(HMASK, hv, 0, 16);
                    float hx1 = __shfl_sync(HMASK, hv, 1, 16);
                    float hx2 = __shfl_sync(HMASK, hv, 2, 16);
                    float hx3 = __shfl_sync(HMASK, hv, 3, 16);

                    float a = fmaf(hx1, Wh1, fmaf(hx0, Wh0, p)) + fmaf(hx3, Wh3, hx2 * Wh2);
                    float z = __cosf(a);

                    float z0 = __shfl_sync(HMASK, z, gbase | 0, 16);
                    float z1 = __shfl_sync(HMASK, z, gbase | 1, 16);
                    float z2 = __shfl_sync(HMASK, z, gbase | 2, 16);
                    float z3 = __shfl_sync(HMASK, z, gbase | 3, 16);

                    float t01 = (m0 ? z0 : 1.0f) * z1;
                    float t23 = (m2 ? z2 : 1.0f) * (m3 ? z3 : 1.0f);
                    float q = t01 * t23;

                    float t = tanh_approx(q * tsc);

                    float ti = __shfl_sync(HMASK, t, 4  | w, 16);
                    float tu = __shfl_sync(HMASK, t, 8  | w, 16);
                    float to = __shfl_sync(HMASK, t, 12 | w, 16);

                    float fv = fmaf(t,  0.5f, 0.5f);
                    float iv = fmaf(ti, 0.5f, 0.5f);
                    float ov = fmaf(to, 0.5f, 0.5f);
                    float c  = fmaf(fv, cx, iv * tu);
                    float hn = ov * tanh_approx(c);

                    cx = c;
                    hv = hn;
                    if (g == 0) sH[(blk * 4 + k) * 4 + w] = hn;
                }

                // publish completed 64-step chunk (consumer + producer pacing)
                if ((blk & 15) == 15) {
                    __threadfence_block();
                    __syncwarp(HMASK);
                    if (lane == 0) sFlag = (blk + 1) >> 4;
                }
            }
        } else {
            // ---- logits + log_softmax consumer ----
            int l = lane - 16;
            float* outb = out + (size_t)b * SS * TT;

            for (int c = 0; c < 8; c++) {
                while (sFlag < c + 1) __nanosleep(192);
                __threadfence_block();

                #pragma unroll
                for (int r = 0; r < 4; r++) {
                    int s = c * 64 + r * 16 + l;
                    float4 h = sH4[s];

                    float lg[TT];
                    #pragma unroll
                    for (int t = 0; t < TT; t++) {
                        float v = sbt[t];
                        v = fmaf(h.x, sWt[0 * TT + t], v);
                        v = fmaf(h.y, sWt[1 * TT + t], v);
                        v = fmaf(h.z, sWt[2 * TT + t], v);
                        v = fmaf(h.w, sWt[3 * TT + t], v);
                        lg[t] = v;
                    }
                    float mx = lg[0];
                    #pragma unroll
                    for (int t = 1; t < TT; t++) mx = fmaxf(mx, lg[t]);
                    float sum = 0.f;
                    #pragma unroll
                    for (int t = 0; t < TT; t++) sum += __expf(lg[t] - mx);
                    float lse = mx + __logf(sum);

                    float2* o2 = (float2*)(outb + (size_t)s * TT);
                    #pragma unroll
                    for (int t = 0; t < TT; t += 2)
                        o2[t >> 1] = make_float2(lg[t] - lse, lg[t + 1] - lse);
                }
            }
        }
    } else if (wid <= 4) {
        // ================= PRE producer (warps 1-4, 128 threads) =================
        int pt = tid - 32;                // 0..127

        for (int c = 0; c < 8; c++) {
            // ring backpressure: chunk c overwrites slot c&3; safe once rec
            // finished chunk c-3 (chunks 0-3 unconditional)
            if (c >= 4) {
                while (sFlag < c - 3) __nanosleep(128);
            }
            float* dst = sPre[c & 3];

            #pragma unroll
            for (int half = 0; half < 2; half++) {
                int task = pt + half * 128;      // 0..255
                int so = task >> 2;              // step within chunk
                int w  = task & 3;
                int s  = c * 64 + so;
                const float4* e4 = (const float4*)(emb + (size_t)x[b * SS + s] * EE);

                float4 A0 = make_float4(0.f, 0.f, 0.f, 0.f);
                float4 A1 = A0, A2 = A0, A3 = A0;
                #pragma unroll
                for (int k4 = 0; k4 < 32; k4++) {
                    float4 e = e4[k4];
                    int k = k4 * 4;
                    float4 w0 = sW4[(k + 0) * 4 + w];
                    float4 w1 = sW4[(k + 1) * 4 + w];
                    float4 w2 = sW4[(k + 2) * 4 + w];
                    float4 w3 = sW4[(k + 3) * 4 + w];
                    A0.x = fmaf(e.x, w0.x, A0.x); A0.y = fmaf(e.x, w0.y, A0.y);
                    A0.z = fmaf(e.x, w0.z, A0.z); A0.w = fmaf(e.x, w0.w, A0.w);
                    A1.x = fmaf(e.y, w1.x, A1.x); A1.y = fmaf(e.y, w1.y, A1.y);
                    A1.z = fmaf(e.y, w1.z, A1.z); A1.w = fmaf(e.y, w1.w, A1.w);
                    A2.x = fmaf(e.z, w2.x, A2.x); A2.y = fmaf(e.z, w2.y, A2.y);
                    A2.z = fmaf(e.z, w2.z, A2.z); A2.w = fmaf(e.z, w2.w, A2.w);
                    A3.x = fmaf(e.w, w3.x, A3.x); A3.y = fmaf(e.w, w3.y, A3.y);
                    A3.z = fmaf(e.w, w3.z, A3.z); A3.w = fmaf(e.w, w3.w, A3.w);
                }
                float4 C = sC4[w];
                float4 r;
                r.x = (A0.x + A1.x) + (A2.x + A3.x) + C.x;
                r.y = (A0.y + A1.y) + (A2.y + A3.y) + C.y;
                r.z = (A0.z + A1.z) + (A2.z + A3.z) + C.z;
                r.w = (A0.w + A1.w) + (A2.w + A3.w) + C.w;
                // [so*16 + w*4 + g] as one float4 store
                ((float4*)dst)[so * 4 + w] = r;
            }

            __syncwarp();
            __threadfence_block();
            if ((tid & 31) == 0) atomicAdd((int*)&sPreCnt[c], 1);
        }
    }
    // warps 5-7: done after init
}

// ---------------------------------------------------------------------------
extern "C" void kernel_launch(void* const* d_in, const int* in_sizes, int n_in,
                              void* d_out, int out_size)
{
    (void)in_sizes; (void)n_in; (void)out_size;
    const int*   x   = (const int*)  d_in[0];
    const float* emb = (const float*)d_in[1];
    const float* Wf  = (const float*)d_in[2];
    const float* bf  = (const float*)d_in[3];
    const float* thf = (const float*)d_in[4];
    const float* Wi  = (const float*)d_in[5];
    const float* bi  = (const float*)d_in[6];
    const float* thi = (const float*)d_in[7];
    const float* Wu  = (const float*)d_in[8];
    const float* bu  = (const float*)d_in[9];
    const float* thu = (const float*)d_in[10];
    const float* Wo  = (const float*)d_in[11];
    const float* bo  = (const float*)d_in[12];
    const float* tho = (const float*)d_in[13];
    const float* Wt  = (const float*)d_in[14];
    const float* bt  = (const float*)d_in[15];
    float* out = (float*)d_out;

    fused_kernel<<<NBLK, 256>>>(x, emb, Wf, bf, thf, Wi, bi, thi,
                                Wu, bu, thu, Wo, bo, tho, Wt, bt, out);
}

// round 14
// speedup vs baseline: 1.0848x; 1.0848x over previous
#include <cuda_runtime.h>

#define BB 64
#define SS 512
#define EE 128
#define TT 10
#define ROWS (BB*SS)

#define NPRE 64
#define NREC 64
#define NBLK (NPRE + NREC)
#define NCHUNK 8          // 8 chunks x 64 steps

// scratch (static device globals: allocation-free, zero-initialized at load)
__device__ float g_pre[ROWS * 16 + 128];  // [row][w*4+g] (+ pad for branchless prefetch)
__device__ int g_cnt[NCHUNK];             // pre chunk counters (monotone across runs)
__device__ int g_sub[4];                  // chunk-0 16-step sub-counters (monotone)
__device__ int g_eb[NREC];                // rec per-block epochs

__device__ __forceinline__ float tanh_approx(float x) {
    float y;
    asm("tanh.approx.f32 %0, %1;" : "=f"(y) : "f"(x));
    return y;
}

// acquire load: plain L2 read, no atomic-ALU serialization
__device__ __forceinline__ int ld_acquire(const int* p) {
    int v;
    asm volatile("ld.acquire.gpu.global.b32 %0, [%1];" : "=r"(v) : "l"(p) : "memory");
    return v;
}

// ---------------------------------------------------------------------------
// One fused kernel, 128 blocks = one per SM (no pre/rec co-residency).
//   [0,64)   pre : 8 s-ordered chunks of 64 steps; block bid handles
//                  s = 64c + bid. Chunk 0 additionally publishes 16-step
//                  sub-counters g_sub[bid>>4] so rec can start early.
//   [64,128) rec : warp 0 only, SPLIT WARP:
//                  lanes 0-15  = recurrence, lanes 16-31 = log-softmax.
// Monotone epoch counters make the protocol graph-replay-safe.
// ---------------------------------------------------------------------------
__global__ void __launch_bounds__(256, 1) fused_kernel(
    const int* __restrict__ x, const float* __restrict__ emb,
    const float* __restrict__ Wf, const float* __restrict__ bf, const float* __restrict__ thf,
    const float* __restrict__ Wi, const float* __restrict__ bi, const float* __restrict__ thi,
    const float* __restrict__ Wu, const float* __restrict__ bu, const float* __restrict__ thu,
    const float* __restrict__ Wo, const float* __restrict__ bo, const float* __restrict__ tho,
    const float* __restrict__ Wt, const float* __restrict__ bt,
    float* __restrict__ out)
{
    const unsigned HMASK = 0xFFFFu;       // rec half-warp
    const unsigned UMASK = 0xFFFF0000u;   // out half-warp
    int bid = blockIdx.x;
    int tid = threadIdx.x;

    __shared__ float4 sW4[EE * 4];     // pre weights
    __shared__ float4 sC4[4];          // pre bias+theta
    __shared__ float4 sH4[SS];         // rec->out hidden states (8KB)
    __shared__ float  sWt[4 * TT];     // out weights
    __shared__ float  sbt[TT];
    __shared__ volatile int sFlag;     // rec progress in 64-step chunks

    if (bid < NPRE) {
        // ================= PRE =================
        for (int idx = tid; idx < EE * 4; idx += 256) {
            int k = idx >> 2, w = idx & 3;
            sW4[idx] = make_float4(Wf[k * 4 + w], Wi[k * 4 + w],
                                   Wu[k * 4 + w], Wo[k * 4 + w]);
        }
        if (tid < 4) {
            sC4[tid] = make_float4(bf[tid] + thf[tid], bi[tid] + thi[tid],
                                   bu[tid] + thu[tid], bo[tid] + tho[tid]);
        }
        __syncthreads();

        int w  = tid & 3;
        int bb = tid >> 2;               // batch 0..63
        float4 C = sC4[w];

        for (int c = 0; c < NCHUNK; c++) {
            int s   = c * 64 + bid;      // bid < 64
            int row = bb * SS + s;
            const float4* e4 = (const float4*)(emb + (size_t)x[row] * EE);

            float4 A0 = make_float4(0.f, 0.f, 0.f, 0.f);
            float4 A1 = A0, A2 = A0, A3 = A0;
            #pragma unroll
            for (int k4 = 0; k4 < 32; k4++) {
                float4 e = e4[k4];
                int k = k4 * 4;
                float4 w0 = sW4[(k + 0) * 4 + w];
                float4 w1 = sW4[(k + 1) * 4 + w];
                float4 w2 = sW4[(k + 2) * 4 + w];
                float4 w3 = sW4[(k + 3) * 4 + w];
                A0.x = fmaf(e.x, w0.x, A0.x); A0.y = fmaf(e.x, w0.y, A0.y);
                A0.z = fmaf(e.x, w0.z, A0.z); A0.w = fmaf(e.x, w0.w, A0.w);
                A1.x = fmaf(e.y, w1.x, A1.x); A1.y = fmaf(e.y, w1.y, A1.y);
                A1.z = fmaf(e.y, w1.z, A1.z); A1.w = fmaf(e.y, w1.w, A1.w);
                A2.x = fmaf(e.z, w2.x, A2.x); A2.y = fmaf(e.z, w2.y, A2.y);
                A2.z = fmaf(e.z, w2.z, A2.z); A2.w = fmaf(e.z, w2.w, A2.w);
                A3.x = fmaf(e.w, w3.x, A3.x); A3.y = fmaf(e.w, w3.y, A3.y);
                A3.z = fmaf(e.w, w3.z, A3.z); A3.w = fmaf(e.w, w3.w, A3.w);
            }
            float4 r;
            r.x = (A0.x + A1.x) + (A2.x + A3.x) + C.x;
            r.y = (A0.y + A1.y) + (A2.y + A3.y) + C.y;
            r.z = (A0.z + A1.z) + (A2.z + A3.z) + C.z;
            r.w = (A0.w + A1.w) + (A2.w + A3.w) + C.w;
            ((float4*)g_pre)[(size_t)row * 4 + w] = r;

            __threadfence();
            __syncthreads();
            if (tid == 0) {
                if (c == 0) atomicAdd(&g_sub[bid >> 4], 1);  // 16-step sub-publish
                atomicAdd(&g_cnt[c], 1);
            }
            __syncthreads();
        }
    } else {
        // ================= REC + OUT (split warp 0) =================
        if (tid >= 32) return;
        int lane = tid;
        int b = bid - NPRE;

        if (lane == 0) sFlag = 0;
        __syncwarp(0xFFFFFFFFu);   // all 32 lanes see sFlag=0 before splitting

        if (lane < 16) {
            // ---- lower half: recurrence ----
            int e = 0;
            if (lane == 0) e = atomicAdd(&g_eb[b], 1) + 1;
            e = __shfl_sync(HMASK, e, 0);
            const int chunk_need = NPRE * e;
            const int sub_need   = 16 * e;

            int g = lane >> 2;
            int w = lane & 3;

            const float* Wg = (g == 0) ? Wf : (g == 1) ? Wi : (g == 2) ? Wu : Wo;
            float Wh0 = Wg[(128 + 0) * 4 + w];
            float Wh1 = Wg[(128 + 1) * 4 + w];
            float Wh2 = Wg[(128 + 2) * 4 + w];
            float Wh3 = Wg[(128 + 3) * 4 + w];

            const bool m0 = (w != 0);
            const bool m2 = (w == 0) | (w >= 2);
            const bool m3 = (w == 0) | (w == 3);
            const float tsc = (g == 2) ? 1.0f : 0.5f;
            const int gbase = lane & 12;

            const float* P = g_pre + (size_t)b * SS * 16 + (w * 4 + g);
            float* sH = (float*)sH4;

            float hv = 0.f, cx = 0.f;

            // wait for sub-chunk 0 (steps 0..15) only
            while (ld_acquire(&g_sub[0]) < sub_need) __nanosleep(64);
            __syncwarp(HMASK);

            float pb0 = P[0 * 16], pb1 = P[1 * 16], pb2 = P[2 * 16], pb3 = P[3 * 16];

            for (int blk = 0; blk < 128; blk++) {
                float pc0 = pb0, pc1 = pb1, pc2 = pb2, pc3 = pb3;

                // within chunk 0: gate prefetch on 16-step sub-counters
                if (blk < 12 && (blk & 3) == 3) {
                    int su = (blk + 1) >> 2;
                    while (ld_acquire(&g_sub[su]) < sub_need) __nanosleep(64);
                    __syncwarp(HMASK);
                }
                // before prefetch crosses into the next 64-step chunk, wait
                if ((blk & 15) == 15 && blk < 127) {
                    int c = (blk + 1) >> 4;
                    while (ld_acquire(&g_cnt[c]) < chunk_need) __nanosleep(128);
                    __syncwarp(HMASK);
                }

                pb0 = P[4 * 16]; pb1 = P[5 * 16]; pb2 = P[6 * 16]; pb3 = P[7 * 16];
                P += 64;

                #pragma unroll
                for (int k = 0; k < 4; k++) {
                    float p = (k == 0) ? pc0 : (k == 1) ? pc1 : (k == 2) ? pc2 : pc3;

                    float hx0 = __shfl_sync(HMASK, hv, 0, 16);
                    float hx1 = __shfl_sync(HMASK, hv, 1, 16);
                    float hx2 = __shfl_sync(HMASK, hv, 2, 16);
                    float hx3 = __shfl_sync(HMASK, hv, 3, 16);

                    // pipelined chain: tail after the LAST shfl (hx3) is 1 fma
                    float a = fmaf(hx3, Wh3,
                               fmaf(hx2, Wh2,
                                 fmaf(hx1, Wh1,
                                   fmaf(hx0, Wh0, p))));
                    float z = __cosf(a);

                    float z0 = __shfl_sync(HMASK, z, gbase | 0, 16);
                    float z1 = __shfl_sync(HMASK, z, gbase | 1, 16);
                    float z2 = __shfl_sync(HMASK, z, gbase | 2, 16);
                    float z3 = __shfl_sync(HMASK, z, gbase | 3, 16);

                    // tail after the LAST shfl (z3) is 1 mul
                    float q = (m0 ? z0 : 1.0f) * z1;
                    q = q * (m2 ? z2 : 1.0f);
                    q = q * (m3 ? z3 : 1.0f);

                    float t = tanh_approx(q * tsc);

                    float ti = __shfl_sync(HMASK, t, 4  | w, 16);
                    float tu = __shfl_sync(HMASK, t, 8  | w, 16);
                    float to = __shfl_sync(HMASK, t, 12 | w, 16);

                    float fv = fmaf(t,  0.5f, 0.5f);
                    float iv = fmaf(ti, 0.5f, 0.5f);
                    float ov = fmaf(to, 0.5f, 0.5f);
                    float c  = fmaf(fv, cx, iv * tu);
                    float hn = ov * tanh_approx(c);

                    cx = c;
                    hv = hn;
                    if (g == 0) sH[(blk * 4 + k) * 4 + w] = hn;
                }

                // publish a 64-step chunk to the upper half
                if ((blk & 15) == 15) {
                    __threadfence_block();
                    __syncwarp(HMASK);
                    if (lane == 0) sFlag = (blk + 1) >> 4;
                }
            }
        } else {
            // ---- upper half: logits + log_softmax consumer ----
            int l = lane - 16;
            for (int idx = l; idx < 4 * TT; idx += 16) sWt[idx] = Wt[idx];
            for (int idx = l; idx < TT; idx += 16) sbt[idx] = bt[idx];
            __syncwarp(UMASK);   // orders the smem weight fills across upper lanes

            float* outb = out + (size_t)b * SS * TT;

            for (int c = 0; c < 8; c++) {
                while (sFlag < c + 1) __nanosleep(192);
                __threadfence_block();

                #pragma unroll
                for (int r = 0; r < 4; r++) {
                    int s = c * 64 + r * 16 + l;
                    float4 h = sH4[s];

                    float lg[TT];
                    #pragma unroll
                    for (int t = 0; t < TT; t++) {
                        float v = sbt[t];
                        v = fmaf(h.x, sWt[0 * TT + t], v);
                        v = fmaf(h.y, sWt[1 * TT + t], v);
                        v = fmaf(h.z, sWt[2 * TT + t], v);
                        v = fmaf(h.w, sWt[3 * TT + t], v);
                        lg[t] = v;
                    }
                    float mx = lg[0];
                    #pragma unroll
                    for (int t = 1; t < TT; t++) mx = fmaxf(mx, lg[t]);
                    float sum = 0.f;
                    #pragma unroll
                    for (int t = 0; t < TT; t++) sum += __expf(lg[t] - mx);
                    float lse = mx + __logf(sum);

                    float2* o2 = (float2*)(outb + (size_t)s * TT);
                    #pragma unroll
                    for (int t = 0; t < TT; t += 2)
                        o2[t >> 1] = make_float2(lg[t] - lse, lg[t + 1] - lse);
                }
            }
        }
    }
}

// ---------------------------------------------------------------------------
extern "C" void kernel_launch(void* const* d_in, const int* in_sizes, int n_in,
                              void* d_out, int out_size)
{
    (void)in_sizes; (void)n_in; (void)out_size;
    const int*   x   = (const int*)  d_in[0];
    const float* emb = (const float*)d_in[1];
    const float* Wf  = (const float*)d_in[2];
    const float* bf  = (const float*)d_in[3];
    const float* thf = (const float*)d_in[4];
    const float* Wi  = (const float*)d_in[5];
    const float* bi  = (const float*)d_in[6];
    const float* thi = (const float*)d_in[7];
    const float* Wu  = (const float*)d_in[8];
    const float* bu  = (const float*)d_in[9];
    const float* thu = (const float*)d_in[10];
    const float* Wo  = (const float*)d_in[11];
    const float* bo  = (const float*)d_in[12];
    const float* tho = (const float*)d_in[13];
    const float* Wt  = (const float*)d_in[14];
    const float* bt  = (const float*)d_in[15];
    float* out = (float*)d_out;

    fused_kernel<<<NBLK, 256>>>(x, emb, Wf, bf, thf, Wi, bi, thi,
                                Wu, bu, thu, Wo, bo, tho, Wt, bt, out);
}

// round 15
// speedup vs baseline: 1.1220x; 1.0343x over previous
#include <cuda_runtime.h>

#define BB 64
#define SS 512
#define EE 128
#define TT 10
#define ROWS (BB*SS)

#define NPRE 64
#define NREC 64
#define NBLK (NPRE + NREC)
#define NCHUNK 8          // 8 chunks x 64 steps

// scratch (static device globals: allocation-free, zero-initialized at load)
__device__ float g_pre[ROWS * 16 + 128];  // [row][w*4+g] (+ pad for branchless prefetch)
__device__ int g_cnt[NCHUNK];             // pre chunk counters (monotone across runs)
__device__ int g_sub[4];                  // chunk-0 16-step sub-counters (monotone)
__device__ int g_eb[NREC];                // rec per-block epochs

__device__ __forceinline__ float tanh_approx(float x) {
    float y;
    asm("tanh.approx.f32 %0, %1;" : "=f"(y) : "f"(x));
    return y;
}

// acquire load: plain L2 read, no atomic-ALU serialization
__device__ __forceinline__ int ld_acquire(const int* p) {
    int v;
    asm volatile("ld.acquire.gpu.global.b32 %0, [%1];" : "=r"(v) : "l"(p) : "memory");
    return v;
}

// ---------------------------------------------------------------------------
// One fused kernel, 128 blocks = one per SM (no pre/rec co-residency).
//   [0,64)   pre : 8 s-ordered chunks of 64 steps; block bid handles
//                  s = 64c + bid. Chunk 0 additionally publishes 16-step
//                  sub-counters g_sub[bid>>4] so rec can start early.
//   [64,128) rec : warp 0 = PURE recurrence (lanes 0-15; 16-31 exit) —
//                  no divergence/foreign issue traffic in the critical warp.
//                  warp 1 = logits + log_softmax consumer (32 lanes,
//                  2 passes of 32 rows per 64-step chunk) via smem sH+sFlag.
// Monotone epoch counters make the protocol graph-replay-safe.
// ---------------------------------------------------------------------------
__global__ void __launch_bounds__(256, 1) fused_kernel(
    const int* __restrict__ x, const float* __restrict__ emb,
    const float* __restrict__ Wf, const float* __restrict__ bf, const float* __restrict__ thf,
    const float* __restrict__ Wi, const float* __restrict__ bi, const float* __restrict__ thi,
    const float* __restrict__ Wu, const float* __restrict__ bu, const float* __restrict__ thu,
    const float* __restrict__ Wo, const float* __restrict__ bo, const float* __restrict__ tho,
    const float* __restrict__ Wt, const float* __restrict__ bt,
    float* __restrict__ out)
{
    const unsigned HMASK = 0xFFFFu;       // rec warp active lanes
    int bid = blockIdx.x;
    int tid = threadIdx.x;

    __shared__ float4 sW4[EE * 4];     // pre weights
    __shared__ float4 sC4[4];          // pre bias+theta
    __shared__ float4 sH4[SS];         // rec->out hidden states (8KB)
    __shared__ float  sWt[4 * TT];     // out weights
    __shared__ float  sbt[TT];
    __shared__ volatile int sFlag;     // rec progress in 64-step chunks

    if (bid < NPRE) {
        // ================= PRE =================
        for (int idx = tid; idx < EE * 4; idx += 256) {
            int k = idx >> 2, w = idx & 3;
            sW4[idx] = make_float4(Wf[k * 4 + w], Wi[k * 4 + w],
                                   Wu[k * 4 + w], Wo[k * 4 + w]);
        }
        if (tid < 4) {
            sC4[tid] = make_float4(bf[tid] + thf[tid], bi[tid] + thi[tid],
                                   bu[tid] + thu[tid], bo[tid] + tho[tid]);
        }
        __syncthreads();

        int w  = tid & 3;
        int bb = tid >> 2;               // batch 0..63
        float4 C = sC4[w];

        for (int c = 0; c < NCHUNK; c++) {
            int s   = c * 64 + bid;      // bid < 64
            int row = bb * SS + s;
            const float4* e4 = (const float4*)(emb + (size_t)x[row] * EE);

            float4 A0 = make_float4(0.f, 0.f, 0.f, 0.f);
            float4 A1 = A0, A2 = A0, A3 = A0;
            #pragma unroll
            for (int k4 = 0; k4 < 32; k4++) {
                float4 e = e4[k4];
                int k = k4 * 4;
                float4 w0 = sW4[(k + 0) * 4 + w];
                float4 w1 = sW4[(k + 1) * 4 + w];
                float4 w2 = sW4[(k + 2) * 4 + w];
                float4 w3 = sW4[(k + 3) * 4 + w];
                A0.x = fmaf(e.x, w0.x, A0.x); A0.y = fmaf(e.x, w0.y, A0.y);
                A0.z = fmaf(e.x, w0.z, A0.z); A0.w = fmaf(e.x, w0.w, A0.w);
                A1.x = fmaf(e.y, w1.x, A1.x); A1.y = fmaf(e.y, w1.y, A1.y);
                A1.z = fmaf(e.y, w1.z, A1.z); A1.w = fmaf(e.y, w1.w, A1.w);
                A2.x = fmaf(e.z, w2.x, A2.x); A2.y = fmaf(e.z, w2.y, A2.y);
                A2.z = fmaf(e.z, w2.z, A2.z); A2.w = fmaf(e.z, w2.w, A2.w);
                A3.x = fmaf(e.w, w3.x, A3.x); A3.y = fmaf(e.w, w3.y, A3.y);
                A3.z = fmaf(e.w, w3.z, A3.z); A3.w = fmaf(e.w, w3.w, A3.w);
            }
            float4 r;
            r.x = (A0.x + A1.x) + (A2.x + A3.x) + C.x;
            r.y = (A0.y + A1.y) + (A2.y + A3.y) + C.y;
            r.z = (A0.z + A1.z) + (A2.z + A3.z) + C.z;
            r.w = (A0.w + A1.w) + (A2.w + A3.w) + C.w;
            ((float4*)g_pre)[(size_t)row * 4 + w] = r;

            __threadfence();
            __syncthreads();
            if (tid == 0) {
                if (c == 0) atomicAdd(&g_sub[bid >> 4], 1);  // 16-step sub-publish
                atomicAdd(&g_cnt[c], 1);
            }
            __syncthreads();
        }
    } else {
        // ================= REC (warp 0) + OUT (warp 1) =================
        int b = bid - NPRE;

        if (tid == 0) sFlag = 0;
        __syncthreads();   // all warps see sFlag=0 (also covers weight fills below)

        if (tid < 32) {
            // ---- warp 0: pure recurrence on lanes 0-15 ----
            if (tid >= 16) return;   // lanes 16-31 retire: zero divergence left
            int lane = tid;

            int e = 0;
            if (lane == 0) e = atomicAdd(&g_eb[b], 1) + 1;
            e = __shfl_sync(HMASK, e, 0);
            const int chunk_need = NPRE * e;
            const int sub_need   = 16 * e;

            int g = lane >> 2;
            int w = lane & 3;

            const float* Wg = (g == 0) ? Wf : (g == 1) ? Wi : (g == 2) ? Wu : Wo;
            float Wh0 = Wg[(128 + 0) * 4 + w];
            float Wh1 = Wg[(128 + 1) * 4 + w];
            float Wh2 = Wg[(128 + 2) * 4 + w];
            float Wh3 = Wg[(128 + 3) * 4 + w];

            const bool m0 = (w != 0);
            const bool m2 = (w == 0) | (w >= 2);
            const bool m3 = (w == 0) | (w == 3);
            const float tsc = (g == 2) ? 1.0f : 0.5f;
            const int gbase = lane & 12;

            const float* P = g_pre + (size_t)b * SS * 16 + (w * 4 + g);
            float* sH = (float*)sH4;

            float hv = 0.f, cx = 0.f;

            // wait for sub-chunk 0 (steps 0..15) only
            while (ld_acquire(&g_sub[0]) < sub_need) __nanosleep(64);
            __syncwarp(HMASK);

            float pb0 = P[0 * 16], pb1 = P[1 * 16], pb2 = P[2 * 16], pb3 = P[3 * 16];

            for (int blk = 0; blk < 128; blk++) {
                float pc0 = pb0, pc1 = pb1, pc2 = pb2, pc3 = pb3;

                // within chunk 0: gate prefetch on 16-step sub-counters
                if (blk < 12 && (blk & 3) == 3) {
                    int su = (blk + 1) >> 2;
                    while (ld_acquire(&g_sub[su]) < sub_need) __nanosleep(64);
                    __syncwarp(HMASK);
                }
                // before prefetch crosses into the next 64-step chunk, wait
                if ((blk & 15) == 15 && blk < 127) {
                    int c = (blk + 1) >> 4;
                    while (ld_acquire(&g_cnt[c]) < chunk_need) __nanosleep(128);
                    __syncwarp(HMASK);
                }

                pb0 = P[4 * 16]; pb1 = P[5 * 16]; pb2 = P[6 * 16]; pb3 = P[7 * 16];
                P += 64;

                #pragma unroll
                for (int k = 0; k < 4; k++) {
                    float p = (k == 0) ? pc0 : (k == 1) ? pc1 : (k == 2) ? pc2 : pc3;

                    float hx0 = __shfl_sync(HMASK, hv, 0, 16);
                    float hx1 = __shfl_sync(HMASK, hv, 1, 16);
                    float hx2 = __shfl_sync(HMASK, hv, 2, 16);
                    float hx3 = __shfl_sync(HMASK, hv, 3, 16);

                    float a = fmaf(hx3, Wh3,
                               fmaf(hx2, Wh2,
                                 fmaf(hx1, Wh1,
                                   fmaf(hx0, Wh0, p))));
                    float z = __cosf(a);

                    float z0 = __shfl_sync(HMASK, z, gbase | 0, 16);
                    float z1 = __shfl_sync(HMASK, z, gbase | 1, 16);
                    float z2 = __shfl_sync(HMASK, z, gbase | 2, 16);
                    float z3 = __shfl_sync(HMASK, z, gbase | 3, 16);

                    float q = (m0 ? z0 : 1.0f) * z1;
                    q = q * (m2 ? z2 : 1.0f);
                    q = q * (m3 ? z3 : 1.0f);

                    float t = tanh_approx(q * tsc);

                    float ti = __shfl_sync(HMASK, t, 4  | w, 16);
                    float tu = __shfl_sync(HMASK, t, 8  | w, 16);
                    float to = __shfl_sync(HMASK, t, 12 | w, 16);

                    float fv = fmaf(t,  0.5f, 0.5f);
                    float iv = fmaf(ti, 0.5f, 0.5f);
                    float ov = fmaf(to, 0.5f, 0.5f);
                    float c  = fmaf(fv, cx, iv * tu);
                    float hn = ov * tanh_approx(c);

                    cx = c;
                    hv = hn;
                    if (g == 0) sH[(blk * 4 + k) * 4 + w] = hn;
                }

                // publish a 64-step chunk to the consumer warp
                if ((blk & 15) == 15) {
                    __threadfence_block();
                    __syncwarp(HMASK);
                    if (lane == 0) sFlag = (blk + 1) >> 4;
                }
            }
        } else if (tid < 64) {
            // ---- warp 1: logits + log_softmax consumer (32 lanes) ----
            int l = tid - 32;
            for (int idx = l; idx < 4 * TT; idx += 32) sWt[idx] = Wt[idx];
            for (int idx = l; idx < TT; idx += 32) sbt[idx] = bt[idx];
            __syncwarp();   // orders smem weight fills across the warp

            float* outb = out + (size_t)b * SS * TT;

            for (int c = 0; c < 8; c++) {
                while (sFlag < c + 1) __nanosleep(192);
                __threadfence_block();

                #pragma unroll
                for (int r = 0; r < 2; r++) {
                    int s = c * 64 + r * 32 + l;
                    float4 h = sH4[s];

                    float lg[TT];
                    #pragma unroll
                    for (int t = 0; t < TT; t++) {
                        float v = sbt[t];
                        v = fmaf(h.x, sWt[0 * TT + t], v);
                        v = fmaf(h.y, sWt[1 * TT + t], v);
                        v = fmaf(h.z, sWt[2 * TT + t], v);
                        v = fmaf(h.w, sWt[3 * TT + t], v);
                        lg[t] = v;
                    }
                    float mx = lg[0];
                    #pragma unroll
                    for (int t = 1; t < TT; t++) mx = fmaxf(mx, lg[t]);
                    float sum = 0.f;
                    #pragma unroll
                    for (int t = 0; t < TT; t++) sum += __expf(lg[t] - mx);
                    float lse = mx + __logf(sum);

                    float2* o2 = (float2*)(outb + (size_t)s * TT);
                    #pragma unroll
                    for (int t = 0; t < TT; t += 2)
                        o2[t >> 1] = make_float2(lg[t] - lse, lg[t + 1] - lse);
                }
            }
        }
        // warps 2-7: retire after init
    }
}

// ---------------------------------------------------------------------------
extern "C" void kernel_launch(void* const* d_in, const int* in_sizes, int n_in,
                              void* d_out, int out_size)
{
    (void)in_sizes; (void)n_in; (void)out_size;
    const int*   x   = (const int*)  d_in[0];
    const float* emb = (const float*)d_in[1];
    const float* Wf  = (const float*)d_in[2];
    const float* bf  = (const float*)d_in[3];
    const float* thf = (const float*)d_in[4];
    const float* Wi  = (const float*)d_in[5];
    const float* bi  = (const float*)d_in[6];
    const float* thi = (const float*)d_in[7];
    const float* Wu  = (const float*)d_in[8];
    const float* bu  = (const float*)d_in[9];
    const float* thu = (const float*)d_in[10];
    const float* Wo  = (const float*)d_in[11];
    const float* bo  = (const float*)d_in[12];
    const float* tho = (const float*)d_in[13];
    const float* Wt  = (const float*)d_in[14];
    const float* bt  = (const float*)d_in[15];
    float* out = (float*)d_out;

    fused_kernel<<<NBLK, 256>>>(x, emb, Wf, bf, thf, Wi, bi, thi,
                                Wu, bu, thu, Wo, bo, tho, Wt, bt, out);
}